// round 15
// baseline (speedup 1.0000x reference)
#include <cuda_runtime.h>

#define ALPHA 0.5f
#define BATA  0.01f
#define LAMDA 0.01f
#define GAMA  0.01f
#define DIM   64
#define BMAX  8192
#define MAXITEMS 64

__device__ int g_starts[BMAX + 1];

// starts[b] = first index i with segids[i] >= b; also zeroes out[0]. int4 path.
__global__ void bounds_kernel(const int* __restrict__ segids, int total, int B,
                              int* __restrict__ starts, float* __restrict__ out) {
    int i = blockIdx.x * blockDim.x + threadIdx.x;
    int base = i << 2;
    if (i == 0) out[0] = 0.0f;
    if (base < total) {
        int prev = (base == 0) ? -1 : __ldg(&segids[base - 1]);
        if (base + 4 <= total) {
            int4 v = ((const int4*)segids)[i];
            for (int s = prev + 1; s <= v.x; ++s) starts[s] = base;
            for (int s = v.x + 1;  s <= v.y; ++s) starts[s] = base + 1;
            for (int s = v.y + 1;  s <= v.z; ++s) starts[s] = base + 2;
            for (int s = v.z + 1;  s <= v.w; ++s) starts[s] = base + 3;
            if (base + 4 == total)
                for (int s = v.w + 1; s <= B; ++s) starts[s] = total;
        } else {
            for (int e = base; e < total; ++e) {
                int cur = __ldg(&segids[e]);
                for (int s = prev + 1; s <= cur; ++s) starts[s] = e;
                prev = cur;
            }
            for (int s = prev + 1; s <= B; ++s) starts[s] = total;
        }
    }
    cudaTriggerProgrammaticLaunchCompletion();
}

template <int NNEG_T>
__global__ __launch_bounds__(128, 12)
void fism_kernel(const float* __restrict__ bu,
                 const float* __restrict__ bi,
                 const float* __restrict__ qi,
                 const float* __restrict__ pu,
                 const float* __restrict__ uin,
                 const int*   __restrict__ users,
                 const int*   __restrict__ pos_items,
                 const int*   __restrict__ neg_items,
                 int n_neg_rt,
                 const int*   __restrict__ hist_items,
                 float* __restrict__ out)
{
    const int n_neg   = (NNEG_T >= 0) ? NNEG_T : n_neg_rt;
    const int n_items = n_neg + 1;          // 51 when templated (<= 56)

    __shared__ int    s_items[MAXITEMS];
    __shared__ float  s_bi[MAXITEMS];
    __shared__ float4 s_part[8][16];
    __shared__ float  s_ue[DIM];
    __shared__ float  s_tp, s_bu, s_loss;

    const int b = blockIdx.x;               // one user per CTA
    const int t = threadIdx.x;              // 0..127

    const float4* __restrict__ pu4 = (const float4*)pu;
    const float4* __restrict__ qi4 = (const float4*)qi;

    // ---- Pre-PDL: independent of bounds_kernel; NO barrier (R6 lesson) ----
    if (t == 64) { s_loss = 0.0f; s_tp = rsqrtf(uin[b]); s_bu = bu[users[b]]; }
    if (t < n_items) {
        int row = (t == 0) ? pos_items[b] : neg_items[b * n_neg + t - 1];
        s_items[t] = row;
        s_bi[t]    = bi[row];
    }

    cudaGridDependencySynchronize();        // g_starts / out-zeroing visible

    const int start = g_starts[b];
    const int end   = g_starts[b + 1];

    // ---- Phase A: 8 groups x 16 lanes, depth-8 gather (one latency epoch) ----
    const int f4 = t & 15;                  // float4 lane within 64-float row
    const int r  = t >> 4;                  // row group 0..7

    const float4 z = make_float4(0.f, 0.f, 0.f, 0.f);
    float4 acc = z;
    {
        int  d[8];
        bool v[8];
        #pragma unroll
        for (int k = 0; k < 8; k++) {
            int i = start + r + (k << 3);
            v[k] = (i < end);
            d[k] = v[k] ? __ldg(&hist_items[i]) : 0;
        }
        #pragma unroll
        for (int k = 0; k < 8; k++) {
            float4 vv = v[k] ? __ldg(&pu4[d[k] * 16 + f4]) : z;
            acc.x += vv.x; acc.y += vv.y; acc.z += vv.z; acc.w += vv.w;
        }
    }
    // Residual rows (segment longer than 64; uncommon)
    for (int i = start + r + 64; i < end; i += 8) {
        float4 vv = __ldg(&pu4[__ldg(&hist_items[i]) * 16 + f4]);
        acc.x += vv.x; acc.y += vv.y; acc.z += vv.z; acc.w += vv.w;
    }
    s_part[r][f4] = acc;
    __syncthreads();

    // ---- Reduce 8 partials per float4 lane; BATA*||ue||^2 ----
    if (t < 16) {
        float4 tt = s_part[0][t];
        #pragma unroll
        for (int rr = 1; rr < 8; rr++) {
            float4 p = s_part[rr][t];
            tt.x += p.x; tt.y += p.y; tt.z += p.z; tt.w += p.w;
        }
        ((float4*)s_ue)[t] = tt;
        float sq = tt.x * tt.x + tt.y * tt.y + tt.z * tt.z + tt.w * tt.w;
        #pragma unroll
        for (int off = 8; off; off >>= 1)
            sq += __shfl_down_sync(0x0000ffffu, sq, off, 16);
        if (t == 0) s_loss += BATA * sq;     // sole writer at this point
    }
    __syncthreads();

    // ---- Phase B: 4 warps, half-warp per item, 7 items each (56 slots) ----
    const int lane = t & 31;
    const int wl   = t >> 5;                // warp 0..3
    const int half = lane >> 4;
    const int fl   = lane & 15;
    const int hw   = (wl << 1) + half;      // half-warp id 0..7

    const float tp  = s_tp;
    const float b_u = s_bu;
    const float4 ue4 = ((const float4*)s_ue)[fl];

    float part[7];
    bool  valid[7];
    float possq = 0.0f;

    #pragma unroll
    for (int k = 0; k < 7; k++) {
        int j = hw + (k << 3);
        valid[k] = (j < n_items);
        part[k] = 0.0f;
        if (valid[k]) {
            float4 q = __ldg(&qi4[s_items[j] * 16 + fl]);
            part[k] = ue4.x * q.x + ue4.y * q.y + ue4.z * q.z + ue4.w * q.w;
            if (j == 0) possq = q.x * q.x + q.y * q.y + q.z * q.z + q.w * q.w;
        }
    }
    #pragma unroll
    for (int off = 8; off; off >>= 1) {
        #pragma unroll
        for (int k = 0; k < 7; k++)
            part[k] += __shfl_down_sync(0xffffffffu, part[k], off, 16);
    }
    if (wl == 0) {                          // item j==0 lives in half-warp 0
        #pragma unroll
        for (int off = 8; off; off >>= 1)
            possq += __shfl_down_sync(0xffffffffu, possq, off, 16);
    }

    float wloss = 0.0f;
    if (fl == 0) {
        #pragma unroll
        for (int k = 0; k < 7; k++) {
            int j = hw + (k << 3);
            if (valid[k]) {
                float bir = s_bi[j];
                float x = tp * part[k] + bir + b_u;
                float s = 1.0f / (1.0f + __expf(-x));
                if (j == 0) {
                    float e = 1.0f - s;
                    wloss += e * e + BATA * possq + LAMDA * bir * bir;
                } else {
                    wloss += s * s;
                }
            }
        }
    }
    wloss += __shfl_down_sync(0xffffffffu, wloss, 16);
    if (lane == 0) atomicAdd(&s_loss, wloss);
    __syncthreads();

    if (t == 0) atomicAdd(out, s_loss + LAMDA * GAMA * b_u * b_u);
}

extern "C" void kernel_launch(void* const* d_in, const int* in_sizes, int n_in,
                              void* d_out, int out_size)
{
    const float* bu          = (const float*)d_in[0];
    const float* bi          = (const float*)d_in[1];
    const float* qi          = (const float*)d_in[2];
    const float* pu          = (const float*)d_in[3];
    const float* uin         = (const float*)d_in[4];
    const int*   users       = (const int*)  d_in[5];
    const int*   pos_items   = (const int*)  d_in[6];
    const int*   neg_items   = (const int*)  d_in[7];
    const int*   hist_items  = (const int*)  d_in[8];
    const int*   hist_segids = (const int*)  d_in[9];

    const int B     = in_sizes[5];
    const int total = in_sizes[8];
    const int n_neg = in_sizes[7] / B;

    float* out = (float*)d_out;

    int* starts;
    cudaGetSymbolAddress((void**)&starts, g_starts);

    int groups = (total + 3) / 4;
    bounds_kernel<<<(groups + 255) / 256, 256>>>(hist_segids, total, B, starts, out);

    cudaLaunchConfig_t cfg = {};
    cfg.gridDim  = dim3(B);
    cfg.blockDim = dim3(128);
    cfg.stream   = 0;
    cudaLaunchAttribute attr[1];
    attr[0].id = cudaLaunchAttributeProgrammaticStreamSerialization;
    attr[0].val.programmaticStreamSerializationAllowed = 1;
    cfg.attrs    = attr;
    cfg.numAttrs = 1;

    if (n_neg == 50) {
        cudaLaunchKernelEx(&cfg, fism_kernel<50>, bu, bi, qi, pu, uin, users,
                           pos_items, neg_items, n_neg, hist_items, out);
    } else {
        cudaLaunchKernelEx(&cfg, fism_kernel<-1>, bu, bi, qi, pu, uin, users,
                           pos_items, neg_items, n_neg, hist_items, out);
    }
}

// round 16
// speedup vs baseline: 1.3209x; 1.3209x over previous
#include <cuda_runtime.h>

#define ALPHA 0.5f
#define BATA  0.01f
#define LAMDA 0.01f
#define GAMA  0.01f
#define DIM   64
#define BMAX  8192
#define MAXITEMS 64

__device__ int g_starts[BMAX + 1];

// starts[b] = first index i with segids[i] >= b; also zeroes out[0]. int4 path.
__global__ void bounds_kernel(const int* __restrict__ segids, int total, int B,
                              int* __restrict__ starts, float* __restrict__ out) {
    int i = blockIdx.x * blockDim.x + threadIdx.x;
    int base = i << 2;
    if (i == 0) out[0] = 0.0f;
    if (base < total) {
        int prev = (base == 0) ? -1 : __ldg(&segids[base - 1]);
        if (base + 4 <= total) {
            int4 v = ((const int4*)segids)[i];
            for (int s = prev + 1; s <= v.x; ++s) starts[s] = base;
            for (int s = v.x + 1;  s <= v.y; ++s) starts[s] = base + 1;
            for (int s = v.y + 1;  s <= v.z; ++s) starts[s] = base + 2;
            for (int s = v.z + 1;  s <= v.w; ++s) starts[s] = base + 3;
            if (base + 4 == total)
                for (int s = v.w + 1; s <= B; ++s) starts[s] = total;
        } else {
            for (int e = base; e < total; ++e) {
                int cur = __ldg(&segids[e]);
                for (int s = prev + 1; s <= cur; ++s) starts[s] = e;
                prev = cur;
            }
            for (int s = prev + 1; s <= B; ++s) starts[s] = total;
        }
    }
    cudaTriggerProgrammaticLaunchCompletion();
}

template <int NNEG_T>
__global__ __launch_bounds__(256)
void fism_kernel(const float* __restrict__ bu,
                 const float* __restrict__ bi,
                 const float* __restrict__ qi,
                 const float* __restrict__ pu,
                 const float* __restrict__ uin,
                 const int*   __restrict__ users,
                 const int*   __restrict__ pos_items,
                 const int*   __restrict__ neg_items,
                 int n_neg_rt, int B,
                 const int*   __restrict__ hist_items,
                 float* __restrict__ out)
{
    const int n_neg   = (NNEG_T >= 0) ? NNEG_T : n_neg_rt;
    const int n_items = n_neg + 1;          // 51 when templated

    __shared__ int    s_items[2][MAXITEMS];
    __shared__ float  s_bi[2][MAXITEMS];
    __shared__ float4 s_part[2][16][16];
    __shared__ float  s_ue[2][DIM];
    __shared__ float  s_tp[2], s_bu[2];
    __shared__ float  s_loss;

    const int b0  = blockIdx.x * 2;
    const int b1  = b0 + 1;
    const bool has1 = (b1 < B);
    const int tid = threadIdx.x;

    const float4* __restrict__ pu4 = (const float4*)pu;
    const float4* __restrict__ qi4 = (const float4*)qi;

    const int lane = tid & 31;
    const int w    = tid >> 5;              // warp 0..7

    // ---- Pre-PDL: independent of bounds_kernel; NO barrier (R6 lesson) ----
    if (tid == 0) s_loss = 0.0f;
    if (tid == 32) { s_tp[0] = rsqrtf(uin[b0]); s_bu[0] = bu[users[b0]]; }
    if (tid == 33) {
        s_tp[1] = has1 ? rsqrtf(uin[b1]) : 0.0f;
        s_bu[1] = has1 ? bu[users[b1]]   : 0.0f;
    }
    if (tid < n_items) {
        int row = (tid == 0) ? pos_items[b0] : neg_items[b0 * n_neg + tid - 1];
        s_items[0][tid] = row;
        s_bi[0][tid]    = bi[row];
    } else if (tid >= 128 && tid < 128 + n_items && has1) {
        int t = tid - 128;
        int row = (t == 0) ? pos_items[b1] : neg_items[b1 * n_neg + t - 1];
        s_items[1][t] = row;
        s_bi[1][t]    = bi[row];
    }

    cudaGridDependencySynchronize();        // g_starts / out-zeroing visible

    const int s0 = g_starts[b0];
    const int e0 = g_starts[b0 + 1];
    const int e1 = has1 ? g_starts[b0 + 2] : e0;   // user1 segment = [e0, e1)

    // ---- Phase A: fused 8-deep gather; idx via 1 LDG + shfl per warp ----
    const int f4 = tid & 15;                // float4 lane within 64-float row
    const int p  = lane >> 4;               // group parity within warp (0/1)
    const int r  = (w << 1) + p;            // row group 0..15

    // Lane l (<16) loads one distinct idx for this warp:
    //   g = l&1 (group parity), k = (l>>1)&3 (batch slot), user = (l>>3)&1
    int myidx;
    {
        int g    = lane & 1;
        int kk   = (lane >> 1) & 3;
        bool u1  = (lane & 8) != 0;
        int i    = (u1 ? e0 : s0) + (w << 1) + g + (kk << 4);
        int lim  = u1 ? e1 : e0;
        bool ok  = (lane < 16) && (i < lim);
        myidx    = ok ? __ldg(&hist_items[i]) : 0;
    }

    const float4 z = make_float4(0.f, 0.f, 0.f, 0.f);
    float4 acc0 = z, acc1 = z;
    {
        int  d0[4], d1[4];
        bool v0[4], v1[4];
        #pragma unroll
        for (int k = 0; k < 4; k++) {
            d0[k] = __shfl_sync(0xffffffffu, myidx, (k << 1) | p);
            d1[k] = __shfl_sync(0xffffffffu, myidx, 8 + ((k << 1) | p));
            v0[k] = (s0 + r + (k << 4)) < e0;
            v1[k] = (e0 + r + (k << 4)) < e1;
        }
        #pragma unroll
        for (int k = 0; k < 4; k++) {
            float4 v = v0[k] ? __ldg(&pu4[d0[k] * 16 + f4]) : z;
            acc0.x += v.x; acc0.y += v.y; acc0.z += v.z; acc0.w += v.w;
        }
        #pragma unroll
        for (int k = 0; k < 4; k++) {
            float4 v = v1[k] ? __ldg(&pu4[d1[k] * 16 + f4]) : z;
            acc1.x += v.x; acc1.y += v.y; acc1.z += v.z; acc1.w += v.w;
        }
    }
    // Residuals (segments longer than 64 rows; rare)
    for (int i = s0 + r + 64; i < e0; i += 16) {
        float4 v = __ldg(&pu4[__ldg(&hist_items[i]) * 16 + f4]);
        acc0.x += v.x; acc0.y += v.y; acc0.z += v.z; acc0.w += v.w;
    }
    for (int i = e0 + r + 64; i < e1; i += 16) {
        float4 v = __ldg(&pu4[__ldg(&hist_items[i]) * 16 + f4]);
        acc1.x += v.x; acc1.y += v.y; acc1.z += v.z; acc1.w += v.w;
    }
    s_part[0][r][f4] = acc0;
    s_part[1][r][f4] = acc1;
    __syncthreads();

    // ---- Reduce both users (threads 0-15: u0, 16-31: u1) ----
    if (tid < 32) {
        int uu = tid >> 4, c = tid & 15;
        float4 t = s_part[uu][0][c];
        #pragma unroll
        for (int rr = 1; rr < 16; rr++) {
            float4 pp = s_part[uu][rr][c];
            t.x += pp.x; t.y += pp.y; t.z += pp.z; t.w += pp.w;
        }
        ((float4*)s_ue[uu])[c] = t;
        float sq = t.x * t.x + t.y * t.y + t.z * t.z + t.w * t.w;
        #pragma unroll
        for (int off = 8; off; off >>= 1)
            sq += __shfl_down_sync(0xffffffffu, sq, off, 16);
        if (c == 0 && (uu == 0 || has1)) atomicAdd(&s_loss, BATA * sq);
    }
    __syncthreads();

    // ---- Phase B: warps 0-3 score user0, warps 4-7 score user1 ----
    const int u    = w >> 2;                // user index 0/1
    const int wl   = w & 3;
    const int half = lane >> 4;
    const int fl   = lane & 15;
    const int hw   = (wl << 1) + half;      // half-warp id 0..7 within user

    const float tp  = s_tp[u];
    const float b_u = s_bu[u];
    const float4 ue4 = ((const float4*)s_ue[u])[fl];
    const bool my_user_ok = (u == 0) || has1;
    const int my_items = my_user_ok ? n_items : 0;

    float part[7];
    bool  valid[7];
    float possq = 0.0f;

    #pragma unroll
    for (int k = 0; k < 7; k++) {
        int j = hw + (k << 3);
        valid[k] = (j < my_items);
        part[k] = 0.0f;
        if (valid[k]) {
            float4 q = __ldg(&qi4[s_items[u][j] * 16 + fl]);
            part[k] = ue4.x * q.x + ue4.y * q.y + ue4.z * q.z + ue4.w * q.w;
            if (j == 0) possq = q.x * q.x + q.y * q.y + q.z * q.z + q.w * q.w;
        }
    }
    #pragma unroll
    for (int off = 8; off; off >>= 1) {
        #pragma unroll
        for (int k = 0; k < 7; k++)
            part[k] += __shfl_down_sync(0xffffffffu, part[k], off, 16);
    }
    if (wl == 0) {                          // item j==0 lives in half 0 of warp 0/4
        #pragma unroll
        for (int off = 8; off; off >>= 1)
            possq += __shfl_down_sync(0xffffffffu, possq, off, 16);
    }

    float wloss = 0.0f;
    if (fl == 0) {
        #pragma unroll
        for (int k = 0; k < 7; k++) {
            int j = hw + (k << 3);
            if (valid[k]) {
                float bir = s_bi[u][j];
                float x = tp * part[k] + bir + b_u;
                float s = 1.0f / (1.0f + __expf(-x));
                if (j == 0) {
                    float e = 1.0f - s;
                    wloss += e * e + BATA * possq + LAMDA * bir * bir;
                } else {
                    wloss += s * s;
                }
            }
        }
    }
    wloss += __shfl_down_sync(0xffffffffu, wloss, 16);
    if (lane == 0) atomicAdd(&s_loss, wloss);

    if (tid == 0) {
        float extra = LAMDA * GAMA * s_bu[0] * s_bu[0];
        if (has1) extra += LAMDA * GAMA * s_bu[1] * s_bu[1];
        atomicAdd(&s_loss, extra);
    }
    __syncthreads();

    if (tid == 0) atomicAdd(out, s_loss);
}

extern "C" void kernel_launch(void* const* d_in, const int* in_sizes, int n_in,
                              void* d_out, int out_size)
{
    const float* bu          = (const float*)d_in[0];
    const float* bi          = (const float*)d_in[1];
    const float* qi          = (const float*)d_in[2];
    const float* pu          = (const float*)d_in[3];
    const float* uin         = (const float*)d_in[4];
    const int*   users       = (const int*)  d_in[5];
    const int*   pos_items   = (const int*)  d_in[6];
    const int*   neg_items   = (const int*)  d_in[7];
    const int*   hist_items  = (const int*)  d_in[8];
    const int*   hist_segids = (const int*)  d_in[9];

    const int B     = in_sizes[5];
    const int total = in_sizes[8];
    const int n_neg = in_sizes[7] / B;

    float* out = (float*)d_out;

    int* starts;
    cudaGetSymbolAddress((void**)&starts, g_starts);

    int groups = (total + 3) / 4;
    bounds_kernel<<<(groups + 255) / 256, 256>>>(hist_segids, total, B, starts, out);

    cudaLaunchConfig_t cfg = {};
    cfg.gridDim  = dim3((B + 1) / 2);
    cfg.blockDim = dim3(256);
    cfg.stream   = 0;
    cudaLaunchAttribute attr[1];
    attr[0].id = cudaLaunchAttributeProgrammaticStreamSerialization;
    attr[0].val.programmaticStreamSerializationAllowed = 1;
    cfg.attrs    = attr;
    cfg.numAttrs = 1;

    if (n_neg == 50) {
        cudaLaunchKernelEx(&cfg, fism_kernel<50>, bu, bi, qi, pu, uin, users,
                           pos_items, neg_items, n_neg, B, hist_items, out);
    } else {
        cudaLaunchKernelEx(&cfg, fism_kernel<-1>, bu, bi, qi, pu, uin, users,
                           pos_items, neg_items, n_neg, B, hist_items, out);
    }
}